// round 7
// baseline (speedup 1.0000x reference)
#include <cuda_runtime.h>
#include <math.h>
#include <stdint.h>

#define NE     128
#define NC     256
#define TILE_M 64
#define BLK    512

#define WSTR   132          // W fp32 row stride (words)
#define ABSTR  132          // batch-split row stride (uint2 units)

// smem byte offsets
#define SM_W     0          // 256*132*4 = 135168 : W fp32 [c][k]
#define SM_AB    135168     // 64*132*8  = 67584  : batch {hi,lo} uint2 [m][k]
#define SM_CST   135168     // overlays AB during epilogue: 32*273*4 = 34944
#define CST_MAT  273
#define SM_BIAS  202752     // 1024
#define SMEM_BYTES 203776

__device__ __forceinline__ uint32_t f2tf(float x) {
    uint32_t r;
    asm("cvt.rna.tf32.f32 %0, %1;" : "=r"(r) : "f"(x));
    return r;
}

#define MMA_TF32(c, a, b0, b1) \
    asm volatile("mma.sync.aligned.m16n8k8.row.col.f32.tf32.tf32.f32 " \
        "{%0,%1,%2,%3}, {%4,%5,%6,%7}, {%8,%9}, {%0,%1,%2,%3};" \
        : "+f"((c)[0]), "+f"((c)[1]), "+f"((c)[2]), "+f"((c)[3]) \
        : "r"((a)[0]), "r"((a)[1]), "r"((a)[2]), "r"((a)[3]), "r"(b0), "r"(b1))

__global__ __launch_bounds__(BLK, 1)
void jastrow_tf32s_kernel(const float* __restrict__ occ,
                          const float* __restrict__ W,
                          const float* __restrict__ bias,
                          float* __restrict__ out,
                          int B)
{
    extern __shared__ char sm[];
    float* Wsh = (float*)(sm + SM_W);
    uint2* AB  = (uint2*)(sm + SM_AB);
    float* cst = (float*)(sm + SM_CST);
    float* bs  = (float*)(sm + SM_BIAS);

    const int tid  = threadIdx.x;
    const int wid  = tid >> 5;       // 0..15 : 16-col strip of W (m dimension)
    const int lane = tid & 31;
    const int lq   = lane >> 2;      // 0..7
    const int lr   = lane & 3;       // 0..3
    const int hw   = tid >> 4;       // half-warp 0..31 (LU)
    const int l    = tid & 15;       // lane in half-warp (LU)

    // ---- load W once: Wsh[c][k] = W[k*256 + c] (coalesced in c) ----
    for (int i = tid; i < NE * NC; i += BLK) {
        int k = i >> 8;
        int c = i & 255;
        Wsh[c * WSTR + k] = W[k * NC + c];
    }
    for (int i = tid; i < NC; i += BLK) bs[i] = bias[i];
    __syncthreads();

    const int ntiles = B / TILE_M;

    for (int tile = blockIdx.x; tile < ntiles; tile += gridDim.x) {
        const int m0 = tile * TILE_M;

        // ---- batch fill: fp32 -> tf32 {hi,lo} split, once per tile ----
        #pragma unroll 2
        for (int i = tid; i < TILE_M * NE / 2; i += BLK) {
            int m = i >> 6;
            int k = (i & 63) * 2;
            float2 v = *(const float2*)(occ + (size_t)(m0 + m) * NE + k);
            uint32_t xh = f2tf(v.x);
            uint32_t xl = f2tf(v.x - __uint_as_float(xh));
            uint32_t yh = f2tf(v.y);
            uint32_t yl = f2tf(v.y - __uint_as_float(yh));
            AB[m * ABSTR + k]     = make_uint2(xh, xl);
            AB[m * ABSTR + k + 1] = make_uint2(yh, yl);
        }
        __syncthreads();

        // ---- GEMM: warp wid -> W cols wid*16..+15 (m), all 64 batch rows (n) ----
        float acc[8][4];
        #pragma unroll
        for (int t = 0; t < 8; t++)
            #pragma unroll
            for (int e = 0; e < 4; e++) acc[t][e] = 0.f;

        const int wr0 = (wid * 16 + lq) * WSTR;        // W row (col c = wid*16+lq)
        const int wr1 = (wid * 16 + lq + 8) * WSTR;    // c + 8

        #pragma unroll 2
        for (int ks = 0; ks < 16; ks++) {
            const int kb = ks * 8 + lr;
            // W fragment (m16 x k8), split once per ks (reused over 8 n-tiles)
            float f0 = Wsh[wr0 + kb];
            float f1 = Wsh[wr1 + kb];
            float f2 = Wsh[wr0 + kb + 4];
            float f3 = Wsh[wr1 + kb + 4];
            uint32_t wh[4], wl[4];
            wh[0] = f2tf(f0); wl[0] = f2tf(f0 - __uint_as_float(wh[0]));
            wh[1] = f2tf(f1); wl[1] = f2tf(f1 - __uint_as_float(wh[1]));
            wh[2] = f2tf(f2); wl[2] = f2tf(f2 - __uint_as_float(wh[2]));
            wh[3] = f2tf(f3); wl[3] = f2tf(f3 - __uint_as_float(wh[3]));

            #pragma unroll
            for (int t = 0; t < 8; t++) {
                const int ar = (t * 8 + lq) * ABSTR + ks * 8 + lr;
                uint2 p0 = AB[ar];          // batch elem (row, k=..lr):  {hi, lo}
                uint2 p1 = AB[ar + 4];      // k = ..lr+4
                MMA_TF32(acc[t], wh, p0.x, p1.x);   // Whi * Ahi
                MMA_TF32(acc[t], wh, p0.y, p1.y);   // Whi * Alo
                MMA_TF32(acc[t], wl, p0.x, p1.x);   // Wlo * Ahi
            }
        }
        __syncthreads();   // GEMM smem reads done before staging overwrites AB

        // ---- epilogue: 2 rounds of 32 matrices ----
        #pragma unroll 1
        for (int s = 0; s < 2; s++) {
            // stage: acc element e of n-tile t: col = wid*16+lq+(e>>1)*8,
            //        row = t*8 + 2*lr + (e&1);  round s covers rows 32s..32s+31
            #pragma unroll
            for (int t = 4 * s; t < 4 * s + 4; t++) {
                #pragma unroll
                for (int e = 0; e < 4; e++) {
                    int c = wid * 16 + lq + ((e >> 1) << 3);
                    int r = t * 8 + 2 * lr + (e & 1) - 32 * s;
                    // j element (rr=c>>4, cc=c&15) -> [mat r][rr*17 + cc]
                    cst[r * CST_MAT + (c >> 4) * 17 + (c & 15)] = acc[t][e] + bs[c];
                }
            }
            __syncthreads();

            // ---- LU with partial pivoting: half-warp hw owns matrix hw ----
            {
                float a[16];
                #pragma unroll
                for (int k = 0; k < 16; k++)
                    a[k] = cst[hw * CST_MAT + k * 17 + l] + (k == l ? 1.f : 0.f);

                bool  done   = false;
                float mylog  = 0.f;
                int   mysign = 1;
                int   pick   = 0;

                #pragma unroll
                for (int k = 0; k < 16; k++) {
                    float v   = done ? -1.f : fabsf(a[k]);
                    int   idx = l;
                    #pragma unroll
                    for (int off = 8; off; off >>= 1) {
                        float ov = __shfl_xor_sync(0xffffffffu, v,   off, 16);
                        int   oi = __shfl_xor_sync(0xffffffffu, idx, off, 16);
                        if (ov > v || (ov == v && oi < idx)) { v = ov; idx = oi; }
                    }
                    const int   p    = idx;
                    const float piv  = __shfl_sync(0xffffffffu, a[k], p, 16);
                    const bool  im_p = (l == p);
                    const float mult = (!done && !im_p) ? (a[k] / piv) : 0.f;
                    #pragma unroll
                    for (int jj = k + 1; jj < 16; jj++) {
                        float pr = __shfl_sync(0xffffffffu, a[jj], p, 16);
                        a[jj] -= mult * pr;
                    }
                    if (im_p) {
                        done = true;
                        pick = k;
                        mylog += logf(fabsf(piv));
                        if (piv < 0.f) mysign = -mysign;
                    }
                }

                int inv = 0;
                #pragma unroll
                for (int t = 0; t < 16; t++) {
                    int pt = __shfl_sync(0xffffffffu, pick, t, 16);
                    inv += (t < l && pt > pick) ? 1 : 0;
                }

                float logsum = mylog;
                int   invsum = inv;
                int   sgn    = mysign;
                #pragma unroll
                for (int off = 8; off; off >>= 1) {
                    logsum += __shfl_xor_sync(0xffffffffu, logsum, off, 16);
                    invsum += __shfl_xor_sync(0xffffffffu, invsum, off, 16);
                    sgn    *= __shfl_xor_sync(0xffffffffu, sgn,    off, 16);
                }

                if (l == 0) {
                    const int g = m0 + s * 32 + hw;
                    float sg = (float)sgn * ((invsum & 1) ? -1.f : 1.f);
                    out[g]     = sg;       // j_sign
                    out[B + g] = logsum;   // j_logabs
                }
            }
            __syncthreads();   // cst reused next round / AB refilled next tile
        }
    }
}

extern "C" void kernel_launch(void* const* d_in, const int* in_sizes, int n_in,
                              void* d_out, int out_size)
{
    const float* occ  = (const float*)d_in[0];   // (B, 128) fp32
    const float* W    = (const float*)d_in[1];   // (128, 256) fp32
    const float* bias = (const float*)d_in[2];   // (256,) fp32
    float* out        = (float*)d_out;           // [sign(B); logabs(B)]
    const int B = in_sizes[0] / NE;

    cudaFuncSetAttribute(jastrow_tf32s_kernel,
                         cudaFuncAttributeMaxDynamicSharedMemorySize, SMEM_BYTES);
    jastrow_tf32s_kernel<<<148, BLK, SMEM_BYTES>>>(occ, W, bias, out, B);
}

// round 10
// speedup vs baseline: 1.3079x; 1.3079x over previous
#include <cuda_runtime.h>
#include <math.h>
#include <stdint.h>

#define NE     128
#define NC     256
#define TILE_M 64
#define BLK    512

#define WSTR   132          // W fp32 row stride (words)
#define ABSTR  132          // batch-split row stride (uint2 units)

// smem byte offsets
#define SM_W     0          // 256*132*4 = 135168 : W fp32 [c][k]
#define SM_AB    135168     // 64*132*8  = 67584  : batch {hi,lo} uint2 [m][k]
#define SM_CST   135168     // overlays AB during epilogue: 64*273*4 = 69888
#define CST_MAT  273
#define SM_BIAS  205056     // 1024
#define SMEM_BYTES 206080

__device__ __forceinline__ uint32_t f2tf(float x) {
    uint32_t r;
    asm("cvt.rna.tf32.f32 %0, %1;" : "=r"(r) : "f"(x));
    return r;
}

#define MMA_TF32(c, a, b0, b1) \
    asm volatile("mma.sync.aligned.m16n8k8.row.col.f32.tf32.tf32.f32 " \
        "{%0,%1,%2,%3}, {%4,%5,%6,%7}, {%8,%9}, {%0,%1,%2,%3};" \
        : "+f"((c)[0]), "+f"((c)[1]), "+f"((c)[2]), "+f"((c)[3]) \
        : "r"((a)[0]), "r"((a)[1]), "r"((a)[2]), "r"((a)[3]), "r"(b0), "r"(b1))

__global__ __launch_bounds__(BLK, 1)
void jastrow_tf32d_kernel(const float* __restrict__ occ,
                          const float* __restrict__ W,
                          const float* __restrict__ bias,
                          float* __restrict__ out,
                          int B)
{
    extern __shared__ char sm[];
    float* Wsh = (float*)(sm + SM_W);
    uint2* AB  = (uint2*)(sm + SM_AB);
    float* cst = (float*)(sm + SM_CST);
    float* bs  = (float*)(sm + SM_BIAS);

    const int tid  = threadIdx.x;
    const int wid  = tid >> 5;       // 0..15 : 16-col strip of W (m dimension)
    const int lane = tid & 31;
    const int lq   = lane >> 2;      // 0..7
    const int lr   = lane & 3;       // 0..3
    const int hw   = tid >> 4;       // half-warp 0..31 (LU: matrices 2hw, 2hw+1)
    const int l    = tid & 15;       // lane in half-warp (LU)

    // ---- load W once: Wsh[c][k] = W[k*256 + c] (coalesced in c) ----
    for (int i = tid; i < NE * NC; i += BLK) {
        int k = i >> 8;
        int c = i & 255;
        Wsh[c * WSTR + k] = W[k * NC + c];
    }
    for (int i = tid; i < NC; i += BLK) bs[i] = bias[i];
    __syncthreads();

    const int ntiles = B / TILE_M;

    for (int tile = blockIdx.x; tile < ntiles; tile += gridDim.x) {
        const int m0 = tile * TILE_M;

        // ---- batch fill: fp32 -> tf32 {hi,lo} split, once per tile ----
        #pragma unroll 2
        for (int i = tid; i < TILE_M * NE / 2; i += BLK) {
            int m = i >> 6;
            int k = (i & 63) * 2;
            float2 v = *(const float2*)(occ + (size_t)(m0 + m) * NE + k);
            uint32_t xh = f2tf(v.x);
            uint32_t xl = f2tf(v.x - __uint_as_float(xh));
            uint32_t yh = f2tf(v.y);
            uint32_t yl = f2tf(v.y - __uint_as_float(yh));
            AB[m * ABSTR + k]     = make_uint2(xh, xl);
            AB[m * ABSTR + k + 1] = make_uint2(yh, yl);
        }
        __syncthreads();

        // ---- GEMM: warp wid -> W cols wid*16..+15 (m), all 64 batch rows (n) ----
        float acc[8][4];
        #pragma unroll
        for (int t = 0; t < 8; t++)
            #pragma unroll
            for (int e = 0; e < 4; e++) acc[t][e] = 0.f;

        const int wr0 = (wid * 16 + lq) * WSTR;
        const int wr1 = (wid * 16 + lq + 8) * WSTR;

        #pragma unroll 2
        for (int ks = 0; ks < 16; ks++) {
            const int kb = ks * 8 + lr;
            float f0 = Wsh[wr0 + kb];
            float f1 = Wsh[wr1 + kb];
            float f2 = Wsh[wr0 + kb + 4];
            float f3 = Wsh[wr1 + kb + 4];
            uint32_t wh[4], wl[4];
            wh[0] = f2tf(f0); wl[0] = f2tf(f0 - __uint_as_float(wh[0]));
            wh[1] = f2tf(f1); wl[1] = f2tf(f1 - __uint_as_float(wh[1]));
            wh[2] = f2tf(f2); wl[2] = f2tf(f2 - __uint_as_float(wh[2]));
            wh[3] = f2tf(f3); wl[3] = f2tf(f3 - __uint_as_float(wh[3]));

            #pragma unroll
            for (int t = 0; t < 8; t++) {
                const int ar = (t * 8 + lq) * ABSTR + ks * 8 + lr;
                uint2 p0 = AB[ar];
                uint2 p1 = AB[ar + 4];
                MMA_TF32(acc[t], wh, p0.x, p1.x);   // Whi * Ahi
                MMA_TF32(acc[t], wh, p0.y, p1.y);   // Whi * Alo
                MMA_TF32(acc[t], wl, p0.x, p1.x);   // Wlo * Ahi
            }
        }
        __syncthreads();   // GEMM smem reads done before staging overwrites AB

        // ---- stage all 64 matrices at once ----
        #pragma unroll
        for (int t = 0; t < 8; t++) {
            #pragma unroll
            for (int e = 0; e < 4; e++) {
                int c = wid * 16 + lq + ((e >> 1) << 3);
                int r = t * 8 + 2 * lr + (e & 1);
                // j element (rr=c>>4, cc=c&15) -> [mat r][rr*17 + cc]
                cst[r * CST_MAT + (c >> 4) * 17 + (c & 15)] = acc[t][e] + bs[c];
            }
        }
        __syncthreads();

        // ---- dual interleaved LU: half-warp hw owns matrices 2hw and 2hw+1 ----
        {
            float a[16], b[16];
            #pragma unroll
            for (int k = 0; k < 16; k++) {
                float d = (k == l) ? 1.f : 0.f;
                a[k] = cst[(2 * hw)     * CST_MAT + k * 17 + l] + d;
                b[k] = cst[(2 * hw + 1) * CST_MAT + k * 17 + l] + d;
            }

            bool  doneA = false,  doneB = false;
            float logA  = 0.f,    logB  = 0.f;
            int   sgnA  = 1,      sgnB  = 1;
            int   pickA = 0,      pickB = 0;

            #pragma unroll
            for (int k = 0; k < 16; k++) {
                // packed argmax: |x| bits (low 4 masked) | (15-l); done lanes -> 0
                uint32_t uA = doneA ? 0u
                    : ((__float_as_uint(fabsf(a[k])) & ~0xFu) | (15u - (uint32_t)l));
                uint32_t uB = doneB ? 0u
                    : ((__float_as_uint(fabsf(b[k])) & ~0xFu) | (15u - (uint32_t)l));
                #pragma unroll
                for (int off = 8; off; off >>= 1) {
                    uint32_t oA = __shfl_xor_sync(0xffffffffu, uA, off, 16);
                    uint32_t oB = __shfl_xor_sync(0xffffffffu, uB, off, 16);
                    uA = (oA > uA) ? oA : uA;
                    uB = (oB > uB) ? oB : uB;
                }
                const int   pA   = 15 - (int)(uA & 15u);
                const int   pB   = 15 - (int)(uB & 15u);
                const float pivA = __shfl_sync(0xffffffffu, a[k], pA, 16);
                const float pivB = __shfl_sync(0xffffffffu, b[k], pB, 16);
                const bool  impA = (l == pA);
                const bool  impB = (l == pB);
                const float mulA = (!doneA && !impA) ? (a[k] / pivA) : 0.f;
                const float mulB = (!doneB && !impB) ? (b[k] / pivB) : 0.f;
                #pragma unroll
                for (int jj = k + 1; jj < 16; jj++) {
                    float prA = __shfl_sync(0xffffffffu, a[jj], pA, 16);
                    float prB = __shfl_sync(0xffffffffu, b[jj], pB, 16);
                    a[jj] -= mulA * prA;
                    b[jj] -= mulB * prB;
                }
                if (impA) {
                    doneA = true; pickA = k;
                    logA += logf(fabsf(pivA));
                    if (pivA < 0.f) sgnA = -sgnA;
                }
                if (impB) {
                    doneB = true; pickB = k;
                    logB += logf(fabsf(pivB));
                    if (pivB < 0.f) sgnB = -sgnB;
                }
            }

            int invA = 0, invB = 0;
            #pragma unroll
            for (int t = 0; t < 16; t++) {
                int ptA = __shfl_sync(0xffffffffu, pickA, t, 16);
                int ptB = __shfl_sync(0xffffffffu, pickB, t, 16);
                invA += (t < l && ptA > pickA) ? 1 : 0;
                invB += (t < l && ptB > pickB) ? 1 : 0;
            }

            #pragma unroll
            for (int off = 8; off; off >>= 1) {
                logA += __shfl_xor_sync(0xffffffffu, logA, off, 16);
                logB += __shfl_xor_sync(0xffffffffu, logB, off, 16);
                invA += __shfl_xor_sync(0xffffffffu, invA, off, 16);
                invB += __shfl_xor_sync(0xffffffffu, invB, off, 16);
                sgnA *= __shfl_xor_sync(0xffffffffu, sgnA, off, 16);
                sgnB *= __shfl_xor_sync(0xffffffffu, sgnB, off, 16);
            }

            if (l == 0) {
                const int g = m0 + 2 * hw;
                out[g]         = (float)sgnA * ((invA & 1) ? -1.f : 1.f);
                out[g + 1]     = (float)sgnB * ((invB & 1) ? -1.f : 1.f);
                out[B + g]     = logA;
                out[B + g + 1] = logB;
            }
        }
        __syncthreads();   // cst dead before next tile's AB fill
    }
}

extern "C" void kernel_launch(void* const* d_in, const int* in_sizes, int n_in,
                              void* d_out, int out_size)
{
    const float* occ  = (const float*)d_in[0];   // (B, 128) fp32
    const float* W    = (const float*)d_in[1];   // (128, 256) fp32
    const float* bias = (const float*)d_in[2];   // (256,) fp32
    float* out        = (float*)d_out;           // [sign(B); logabs(B)]
    const int B = in_sizes[0] / NE;

    cudaFuncSetAttribute(jastrow_tf32d_kernel,
                         cudaFuncAttributeMaxDynamicSharedMemorySize, SMEM_BYTES);
    jastrow_tf32d_kernel<<<148, BLK, SMEM_BYTES>>>(occ, W, bias, out, B);
}

// round 11
// speedup vs baseline: 1.3402x; 1.0247x over previous
#include <cuda_runtime.h>
#include <math.h>
#include <stdint.h>

#define NE     128
#define NC     256
#define TILE_M 64
#define BLK    512
#define GRID   148

// smem: AB (swizzled uint2 hi/lo, pad-free) + cst (separate, padded)
#define SM_AB    0            // 64*128*8 = 65536
#define SM_CST   65536        // 64*273*4 = 69888
#define CST_MAT  273
#define SMEM_BYTES 135424

__device__ __forceinline__ uint32_t f2tf(float x) {
    uint32_t r;
    asm("cvt.rna.tf32.f32 %0, %1;" : "=r"(r) : "f"(x));
    return r;
}

#define MMA_TF32(c, a, b0, b1) \
    asm volatile("mma.sync.aligned.m16n8k8.row.col.f32.tf32.tf32.f32 " \
        "{%0,%1,%2,%3}, {%4,%5,%6,%7}, {%8,%9}, {%0,%1,%2,%3};" \
        : "+f"((c)[0]), "+f"((c)[1]), "+f"((c)[2]), "+f"((c)[3]) \
        : "r"((a)[0]), "r"((a)[1]), "r"((a)[2]), "r"((a)[3]), "r"(b0), "r"(b1))

__global__ __launch_bounds__(BLK, 1)
void jastrow_wreg_kernel(const float* __restrict__ occ,
                         const float* __restrict__ W,
                         const float* __restrict__ bias,
                         float* __restrict__ out,
                         int B)
{
    extern __shared__ char sm[];
    uint2* AB  = (uint2*)(sm + SM_AB);
    float* cst = (float*)(sm + SM_CST);

    const int tid  = threadIdx.x;
    const int wid  = tid >> 5;       // 0..15 : 16-col strip of W
    const int lane = tid & 31;
    const int lq   = lane >> 2;      // 0..7
    const int lr   = lane & 3;       // 0..3
    const int hw   = tid >> 4;       // half-warp 0..31 (LU: matrices 2hw, 2hw+1)
    const int l    = tid & 15;       // lane in half-warp (LU)

    // ---- W fragment permanently in registers: 64 fp32 per thread ----
    float wreg[64];
    #pragma unroll
    for (int ks = 0; ks < 16; ks++)
        #pragma unroll
        for (int j = 0; j < 4; j++) {
            int k = ks * 8 + lr + ((j >> 1) << 2);
            int c = wid * 16 + lq + ((j & 1) << 3);
            wreg[ks * 4 + j] = W[k * NC + c];
        }
    const float bias0 = bias[wid * 16 + lq];
    const float bias1 = bias[wid * 16 + lq + 8];

    const int ntiles = B / TILE_M;

    // ---- prologue: fill AB for first tile ----
    {
        const int m0 = blockIdx.x * TILE_M;
        #pragma unroll
        for (int it = 0; it < 8; it++) {
            int i = tid + it * BLK;
            int m = i >> 6;
            int k = (i & 63) * 2;
            float2 v = *(const float2*)(occ + (size_t)(m0 + m) * NE + k);
            uint32_t xh = f2tf(v.x);
            uint32_t xl = f2tf(v.x - __uint_as_float(xh));
            uint32_t yh = f2tf(v.y);
            uint32_t yl = f2tf(v.y - __uint_as_float(yh));
            int idx2 = m * 128 + (k ^ ((m & 7) << 2));
            *(uint4*)&AB[idx2] = make_uint4(xh, xl, yh, yl);
        }
    }
    __syncthreads();

    for (int tile = blockIdx.x; tile < ntiles; tile += GRID) {
        const int m0 = tile * TILE_M;
        const int pnext = (tile + GRID < ntiles) ? tile + GRID : tile;

        // ---- GEMM: warp wid -> W cols wid*16..+15 (m), all 64 batch rows (n) ----
        float acc[8][4];
        #pragma unroll
        for (int t = 0; t < 8; t++)
            #pragma unroll
            for (int e = 0; e < 4; e++) acc[t][e] = 0.f;

        #pragma unroll
        for (int ks = 0; ks < 16; ks++) {
            uint32_t wh[4], wl[4];
            #pragma unroll
            for (int j = 0; j < 4; j++) {
                float f = wreg[ks * 4 + j];
                wh[j] = f2tf(f);
                wl[j] = f2tf(f - __uint_as_float(wh[j]));
            }
            const int q = (ks * 8 + lr) ^ (lq << 2);   // swizzled k-index (row&7 == lq)
            #pragma unroll
            for (int t = 0; t < 8; t++) {
                const int ar0 = (t * 8 + lq) * 128 + q;
                uint2 p0 = AB[ar0];          // {hi,lo} of element (row, kb)
                uint2 p1 = AB[ar0 ^ 4];      // {hi,lo} of element (row, kb+4)
                MMA_TF32(acc[t], wh, p0.x, p1.x);   // Whi * Ahi
                MMA_TF32(acc[t], wh, p0.y, p1.y);   // Whi * Alo
                MMA_TF32(acc[t], wl, p0.x, p1.x);   // Wlo * Ahi
            }
        }

        // ---- prefetch next tile's occ rows into registers (latency hidden by stage+LU) ----
        float2 pf[8];
        #pragma unroll
        for (int it = 0; it < 8; it++) {
            int i = tid + it * BLK;
            int m = i >> 6;
            int k = (i & 63) * 2;
            pf[it] = *(const float2*)(occ + (size_t)(pnext * TILE_M + m) * NE + k);
        }

        // ---- stage all 64 matrices into cst (disjoint from AB: no pre-sync needed) ----
        #pragma unroll
        for (int t = 0; t < 8; t++) {
            #pragma unroll
            for (int e = 0; e < 4; e++) {
                int c = wid * 16 + lq + ((e >> 1) << 3);
                int r = t * 8 + 2 * lr + (e & 1);
                float bv = (e >> 1) ? bias1 : bias0;
                // j element (rr=c>>4, cc=c&15) -> [mat r][rr*17 + cc]
                cst[r * CST_MAT + (c >> 4) * 17 + (c & 15)] = acc[t][e] + bv;
            }
        }
        __syncthreads();   // cst complete; all GEMM AB reads also done

        // ---- dual interleaved LU: half-warp hw owns matrices 2hw and 2hw+1 ----
        {
            float a[16], b[16];
            #pragma unroll
            for (int k = 0; k < 16; k++) {
                float d = (k == l) ? 1.f : 0.f;
                a[k] = cst[(2 * hw)     * CST_MAT + k * 17 + l] + d;
                b[k] = cst[(2 * hw + 1) * CST_MAT + k * 17 + l] + d;
            }

            bool  doneA = false,  doneB = false;
            float logA  = 0.f,    logB  = 0.f;
            int   sgnA  = 1,      sgnB  = 1;
            int   pickA = 0,      pickB = 0;

            #pragma unroll
            for (int k = 0; k < 16; k++) {
                uint32_t uA = doneA ? 0u
                    : ((__float_as_uint(fabsf(a[k])) & ~0xFu) | (15u - (uint32_t)l));
                uint32_t uB = doneB ? 0u
                    : ((__float_as_uint(fabsf(b[k])) & ~0xFu) | (15u - (uint32_t)l));
                #pragma unroll
                for (int off = 8; off; off >>= 1) {
                    uint32_t oA = __shfl_xor_sync(0xffffffffu, uA, off, 16);
                    uint32_t oB = __shfl_xor_sync(0xffffffffu, uB, off, 16);
                    uA = (oA > uA) ? oA : uA;
                    uB = (oB > uB) ? oB : uB;
                }
                const int   pA   = 15 - (int)(uA & 15u);
                const int   pB   = 15 - (int)(uB & 15u);
                const float pivA = __shfl_sync(0xffffffffu, a[k], pA, 16);
                const float pivB = __shfl_sync(0xffffffffu, b[k], pB, 16);
                const bool  impA = (l == pA);
                const bool  impB = (l == pB);
                const float mulA = (!doneA && !impA) ? (a[k] / pivA) : 0.f;
                const float mulB = (!doneB && !impB) ? (b[k] / pivB) : 0.f;
                #pragma unroll
                for (int jj = k + 1; jj < 16; jj++) {
                    float prA = __shfl_sync(0xffffffffu, a[jj], pA, 16);
                    float prB = __shfl_sync(0xffffffffu, b[jj], pB, 16);
                    a[jj] -= mulA * prA;
                    b[jj] -= mulB * prB;
                }
                if (impA) {
                    doneA = true; pickA = k;
                    logA += logf(fabsf(pivA));
                    if (pivA < 0.f) sgnA = -sgnA;
                }
                if (impB) {
                    doneB = true; pickB = k;
                    logB += logf(fabsf(pivB));
                    if (pivB < 0.f) sgnB = -sgnB;
                }
            }

            int invA = 0, invB = 0;
            #pragma unroll
            for (int t = 0; t < 16; t++) {
                int ptA = __shfl_sync(0xffffffffu, pickA, t, 16);
                int ptB = __shfl_sync(0xffffffffu, pickB, t, 16);
                invA += (t < l && ptA > pickA) ? 1 : 0;
                invB += (t < l && ptB > pickB) ? 1 : 0;
            }

            #pragma unroll
            for (int off = 8; off; off >>= 1) {
                logA += __shfl_xor_sync(0xffffffffu, logA, off, 16);
                logB += __shfl_xor_sync(0xffffffffu, logB, off, 16);
                invA += __shfl_xor_sync(0xffffffffu, invA, off, 16);
                invB += __shfl_xor_sync(0xffffffffu, invB, off, 16);
                sgnA *= __shfl_xor_sync(0xffffffffu, sgnA, off, 16);
                sgnB *= __shfl_xor_sync(0xffffffffu, sgnB, off, 16);
            }

            if (l == 0) {
                const int g = m0 + 2 * hw;
                out[g]         = (float)sgnA * ((invA & 1) ? -1.f : 1.f);
                out[g + 1]     = (float)sgnB * ((invB & 1) ? -1.f : 1.f);
                out[B + g]     = logA;
                out[B + g + 1] = logB;
            }
        }

        // ---- split + store prefetched next tile into AB (safe: GEMM reads drained at sync above) ----
        #pragma unroll
        for (int it = 0; it < 8; it++) {
            int i = tid + it * BLK;
            int m = i >> 6;
            int k = (i & 63) * 2;
            float2 v = pf[it];
            uint32_t xh = f2tf(v.x);
            uint32_t xl = f2tf(v.x - __uint_as_float(xh));
            uint32_t yh = f2tf(v.y);
            uint32_t yl = f2tf(v.y - __uint_as_float(yh));
            int idx2 = m * 128 + (k ^ ((m & 7) << 2));
            *(uint4*)&AB[idx2] = make_uint4(xh, xl, yh, yl);
        }
        __syncthreads();   // AB(n+1) ready; cst reusable
    }
}

extern "C" void kernel_launch(void* const* d_in, const int* in_sizes, int n_in,
                              void* d_out, int out_size)
{
    const float* occ  = (const float*)d_in[0];   // (B, 128) fp32
    const float* W    = (const float*)d_in[1];   // (128, 256) fp32
    const float* bias = (const float*)d_in[2];   // (256,) fp32
    float* out        = (float*)d_out;           // [sign(B); logabs(B)]
    const int B = in_sizes[0] / NE;

    cudaFuncSetAttribute(jastrow_wreg_kernel,
                         cudaFuncAttributeMaxDynamicSharedMemorySize, SMEM_BYTES);
    jastrow_wreg_kernel<<<GRID, BLK, SMEM_BYTES>>>(occ, W, bias, out, B);
}